// round 12
// baseline (speedup 1.0000x reference)
#include <cuda_runtime.h>

#define BN 2
#define NN 512
#define TT 24
#define HH 8
#define DD 8
#define EE 64
#define SCALE 0.125f
#define LOG2E 1.44269504088896340736f

typedef unsigned long long u64;

// Intermediate per-head attention output (b, n, t, e) before output projection.
__device__ float g_mid[BN * NN * TT * EE];

__device__ __forceinline__ float fast_exp2(float x) {
    float y;
    asm("ex2.approx.f32 %0, %1;" : "=f"(y) : "f"(x));
    return y;
}
__device__ __forceinline__ u64 pack2(float a, float b) {
    u64 r; asm("mov.b64 %0, {%1, %2};" : "=l"(r) : "f"(a), "f"(b)); return r;
}
__device__ __forceinline__ void unpack2(u64 v, float& a, float& b) {
    asm("mov.b64 {%0, %1}, %2;" : "=f"(a), "=f"(b) : "l"(v));
}
__device__ __forceinline__ u64 fma2(u64 a, u64 b, u64 c) {
    u64 d; asm("fma.rn.f32x2 %0, %1, %2, %3;" : "=l"(d) : "l"(a), "l"(b), "l"(c)); return d;
}
__device__ __forceinline__ u64 add2(u64 a, u64 b) {
    u64 d; asm("add.rn.f32x2 %0, %1, %2;" : "=l"(d) : "l"(a), "l"(b)); return d;
}

// One CTA per (b, t, h, query-half): 256 threads, 1 query/thread, 8 keys/iter.
// grid = 768, __launch_bounds__(256,4) -> 32 warps/SM (8/SMSP), ~60 regs state.
// Per-iter slot economy matches R3 (32 LDS.128 / 68 fma2 / 8 MUFU) but with
// half the register state and double the warps for latency cover.
__global__ __launch_bounds__(256, 4) void attn_kernel(
    const float* __restrict__ Vg, const float* __restrict__ Kg, const float* __restrict__ Qg,
    const float* __restrict__ Wv, const float* __restrict__ Wk, const float* __restrict__ Wq)
{
    __shared__ float sKT[DD * NN];   // sKT[j*NN + k]   (16 KB)
    __shared__ float sVT[DD * NN];   // sVT[j*NN + k]   (16 KB)
    __shared__ float sWk[DD * DD], sWv[DD * DD], sWq[DD * DD];

    const int tid = threadIdx.x;
    const int gid  = blockIdx.x >> 1;
    const int half = blockIdx.x & 1;
    const int h = gid & (HH - 1);
    const int t = (gid >> 3) % TT;
    const int b = gid / (HH * TT);

    if (tid < DD * DD) {
        sWv[tid] = Wv[tid];
        sWk[tid] = Wk[tid];
        sWq[tid] = Wq[tid];
    }
    __syncthreads();

    const size_t base = ((size_t)b * NN * TT + t) * EE + (size_t)h * DD;
    const int rowstride = TT * EE;  // 1536 floats between nodes

    // ---- Project K and V (both transposed) for all 512 nodes ----
    for (int r = tid; r < NN; r += 256) {
        const float4* kp = (const float4*)(Kg + base + (size_t)r * rowstride);
        const float4* vp = (const float4*)(Vg + base + (size_t)r * rowstride);
        float4 ka = kp[0], kb = kp[1];
        float4 va = vp[0], vb = vp[1];
        float kr[8] = {ka.x, ka.y, ka.z, ka.w, kb.x, kb.y, kb.z, kb.w};
        float vr[8] = {va.x, va.y, va.z, va.w, vb.x, vb.y, vb.z, vb.w};
        #pragma unroll
        for (int i = 0; i < DD; i++) {
            float sk = 0.f, sv = 0.f;
            #pragma unroll
            for (int j = 0; j < DD; j++) {
                sk = fmaf(kr[j], sWk[i * DD + j], sk);
                sv = fmaf(vr[j], sWv[i * DD + j], sv);
            }
            sKT[i * NN + r] = sk;    // consecutive lanes -> consecutive banks
            sVT[i * NN + r] = sv;
        }
    }

    // ---- Project this thread's query; fold scale*log2e; pack dup ----
    const int q = half * 256 + tid;
    u64 qp[8];
    {
        const float4* qptr = (const float4*)(Qg + base + (size_t)q * rowstride);
        float4 qa = qptr[0], qb = qptr[1];
        float qr[8] = {qa.x, qa.y, qa.z, qa.w, qb.x, qb.y, qb.z, qb.w};
        #pragma unroll
        for (int i = 0; i < DD; i++) {
            float s = 0.f;
            #pragma unroll
            for (int j = 0; j < DD; j++) s = fmaf(qr[j], sWq[i * DD + j], s);
            s *= (SCALE * LOG2E);
            qp[i] = pack2(s, s);
        }
    }
    __syncthreads();

    // ---- Main loop: 8 keys per iteration (64 iters). All SMEM reads are
    //      LDS.128 warp broadcasts. Scores: 4 independent packed chains.
    u64 acc[8];
    #pragma unroll
    for (int j = 0; j < 8; j++) acc[j] = 0;
    u64 lp = 0;

    #pragma unroll 1
    for (int k = 0; k < NN; k += 8) {
        u64 s01 = 0, s23 = 0, s45 = 0, s67 = 0;
        #pragma unroll
        for (int j = 0; j < DD; j++) {
            ulonglong2 kv0 = *(const ulonglong2*)(sKT + j * NN + k);      // keys k..k+3
            ulonglong2 kv1 = *(const ulonglong2*)(sKT + j * NN + k + 4);  // keys k+4..k+7
            s01 = fma2(kv0.x, qp[j], s01);
            s23 = fma2(kv0.y, qp[j], s23);
            s45 = fma2(kv1.x, qp[j], s45);
            s67 = fma2(kv1.y, qp[j], s67);
        }
        float a0, a1, a2, a3, a4, a5, a6, a7;
        unpack2(s01, a0, a1); unpack2(s23, a2, a3);
        unpack2(s45, a4, a5); unpack2(s67, a6, a7);
        u64 p01 = pack2(fast_exp2(a0), fast_exp2(a1));
        u64 p23 = pack2(fast_exp2(a2), fast_exp2(a3));
        u64 p45 = pack2(fast_exp2(a4), fast_exp2(a5));
        u64 p67 = pack2(fast_exp2(a6), fast_exp2(a7));
        lp = add2(lp, p01); lp = add2(lp, p23);
        lp = add2(lp, p45); lp = add2(lp, p67);

        #pragma unroll
        for (int j = 0; j < DD; j++) {
            ulonglong2 vv0 = *(const ulonglong2*)(sVT + j * NN + k);
            ulonglong2 vv1 = *(const ulonglong2*)(sVT + j * NN + k + 4);
            u64 a = fma2(p01, vv0.x, acc[j]);
            a = fma2(p23, vv0.y, a);
            a = fma2(p45, vv1.x, a);
            acc[j] = fma2(p67, vv1.y, a);
        }
    }

    // ---- Epilogue: fold packed halves, normalize, store ----
    float l0, l1;
    unpack2(lp, l0, l1);
    const float inv = 1.0f / (l0 + l1);
    float o[8];
    #pragma unroll
    for (int j = 0; j < 8; j++) {
        float x, y;
        unpack2(acc[j], x, y);
        o[j] = (x + y) * inv;
    }
    float* op = g_mid + base + (size_t)q * rowstride;
    ((float4*)op)[0] = make_float4(o[0], o[1], o[2], o[3]);
    ((float4*)op)[1] = make_float4(o[4], o[5], o[6], o[7]);
}

// Output projection: y[r,:] = x[r,:] @ Wo^T + bo, R = B*N*T = 24576 rows.
// (R7 configuration, 16.5us: protected.)
#define PRPB 64
#define PXS 68
#define PWS 68

__global__ __launch_bounds__(256) void proj_kernel(
    const float* __restrict__ Wo, const float* __restrict__ bo, float* __restrict__ out)
{
    __shared__ float sWT[EE * PWS];
    __shared__ float sb[EE];
    __shared__ float sx[PRPB * PXS];

    const int tid = threadIdx.x;
    for (int idx = tid; idx < EE * EE; idx += 256) {
        int i = idx >> 6, j = idx & 63;
        sWT[j * PWS + i] = Wo[idx];
    }
    if (tid < EE) sb[tid] = bo[tid];

    const size_t rbase = (size_t)blockIdx.x * PRPB * EE;
    #pragma unroll
    for (int idx = tid * 4; idx < PRPB * EE; idx += 256 * 4) {
        float4 v = *(const float4*)(g_mid + rbase + idx);
        float* dst = sx + (idx >> 6) * PXS + (idx & 63);
        dst[0] = v.x; dst[1] = v.y; dst[2] = v.z; dst[3] = v.w;
    }
    __syncthreads();

    const int w = tid >> 5;
    const int lane = tid & 31;
    const int i0 = w * 8;

    u64 aA[4], aB[4];
    {
        u64 b01 = pack2(sb[i0 + 0], sb[i0 + 1]);
        u64 b23 = pack2(sb[i0 + 2], sb[i0 + 3]);
        u64 b45 = pack2(sb[i0 + 4], sb[i0 + 5]);
        u64 b67 = pack2(sb[i0 + 6], sb[i0 + 7]);
        aA[0] = b01; aA[1] = b23; aA[2] = b45; aA[3] = b67;
        aB[0] = b01; aB[1] = b23; aB[2] = b45; aB[3] = b67;
    }

    const float* xA = sx + lane * PXS;
    const float* xB = sx + (lane + 32) * PXS;
    #pragma unroll 4
    for (int j4 = 0; j4 < EE; j4 += 4) {
        float4 xa4 = *(const float4*)(xA + j4);
        float4 xb4 = *(const float4*)(xB + j4);
        const float xa[4] = {xa4.x, xa4.y, xa4.z, xa4.w};
        const float xb[4] = {xb4.x, xb4.y, xb4.z, xb4.w};
        #pragma unroll
        for (int jj = 0; jj < 4; jj++) {
            const ulonglong2* wp = (const ulonglong2*)(sWT + (j4 + jj) * PWS + i0);
            ulonglong2 wa = wp[0];
            ulonglong2 wb = wp[1];
            u64 xpa = pack2(xa[jj], xa[jj]);
            u64 xpb = pack2(xb[jj], xb[jj]);
            aA[0] = fma2(xpa, wa.x, aA[0]);
            aA[1] = fma2(xpa, wa.y, aA[1]);
            aA[2] = fma2(xpa, wb.x, aA[2]);
            aA[3] = fma2(xpa, wb.y, aA[3]);
            aB[0] = fma2(xpb, wa.x, aB[0]);
            aB[1] = fma2(xpb, wa.y, aB[1]);
            aB[2] = fma2(xpb, wb.x, aB[2]);
            aB[3] = fma2(xpb, wb.y, aB[3]);
        }
    }

    __syncthreads();
    #pragma unroll
    for (int r = 0; r < 2; r++) {
        const u64* a = r ? aB : aA;
        float* dst = sx + (lane + r * 32) * PXS + i0;
        #pragma unroll
        for (int c = 0; c < 4; c++) {
            float lo, hi;
            unpack2(a[c], lo, hi);
            dst[2 * c] = lo;
            dst[2 * c + 1] = hi;
        }
    }
    __syncthreads();
    #pragma unroll
    for (int idx = tid * 4; idx < PRPB * EE; idx += 256 * 4) {
        const float* src = sx + (idx >> 6) * PXS + (idx & 63);
        *(float4*)(out + rbase + idx) = make_float4(src[0], src[1], src[2], src[3]);
    }
}

extern "C" void kernel_launch(void* const* d_in, const int* in_sizes, int n_in,
                              void* d_out, int out_size)
{
    const float* values = (const float*)d_in[0];
    const float* keys   = (const float*)d_in[1];
    const float* query  = (const float*)d_in[2];
    const float* Wv     = (const float*)d_in[3];
    const float* Wk     = (const float*)d_in[4];
    const float* Wq     = (const float*)d_in[5];
    const float* Wo     = (const float*)d_in[6];
    const float* bo     = (const float*)d_in[7];

    attn_kernel<<<BN * TT * HH * 2, 256>>>(values, keys, query, Wv, Wk, Wq);
    proj_kernel<<<BN * NN * TT / PRPB, 256>>>(Wo, bo, (float*)d_out);
}

// round 13
// speedup vs baseline: 1.3026x; 1.3026x over previous
#include <cuda_runtime.h>

#define BN 2
#define NN 512
#define NK 256      // keys per CTA (key-split in 2 halves)
#define TT 24
#define HH 8
#define DD 8
#define EE 64
#define SCALE 0.125f
#define LOG2E 1.44269504088896340736f

typedef unsigned long long u64;

// Partial (unnormalized) attention outputs per key-half, g_mid layout (b,n,t,e).
__device__ float g_pacc0[BN * NN * TT * EE];
__device__ float g_pacc1[BN * NN * TT * EE];
// Partial softmax denominators per (b,n,t,h).
__device__ float g_pl0[BN * NN * TT * HH];
__device__ float g_pl1[BN * NN * TT * HH];

__device__ __forceinline__ float fast_exp2(float x) {
    float y;
    asm("ex2.approx.f32 %0, %1;" : "=f"(y) : "f"(x));
    return y;
}
__device__ __forceinline__ u64 pack2(float a, float b) {
    u64 r; asm("mov.b64 %0, {%1, %2};" : "=l"(r) : "f"(a), "f"(b)); return r;
}
__device__ __forceinline__ void unpack2(u64 v, float& a, float& b) {
    asm("mov.b64 {%0, %1}, %2;" : "=f"(a), "=f"(b) : "l"(v));
}
__device__ __forceinline__ u64 fma2(u64 a, u64 b, u64 c) {
    u64 d; asm("fma.rn.f32x2 %0, %1, %2, %3;" : "=l"(d) : "l"(a), "l"(b), "l"(c)); return d;
}
__device__ __forceinline__ u64 add2(u64 a, u64 b) {
    u64 d; asm("add.rn.f32x2 %0, %1, %2;" : "=l"(d) : "l"(a), "l"(b)); return d;
}

// One CTA per (b, t, h, key-half): 256 threads, 2 queries/thread, 256 keys.
// Inner loop is byte-identical in structure to the proven R3 economy
// (16 LDS.128 / 68 fma2 / 8 MUFU per 4-key iter); only the key range shrank.
// grid = 768, occ 2 -> 3 rounds of half-length CTAs (was 2 rounds of full).
__global__ __launch_bounds__(256, 2) void attn_kernel(
    const float* __restrict__ Vg, const float* __restrict__ Kg, const float* __restrict__ Qg,
    const float* __restrict__ Wv, const float* __restrict__ Wk, const float* __restrict__ Wq)
{
    __shared__ float sKT[DD * NK];   // sKT[j*NK + k]   (8 KB)
    __shared__ float sVT[DD * NK];   // sVT[j*NK + k]   (8 KB)
    __shared__ float sWk[DD * DD], sWv[DD * DD], sWq[DD * DD];

    const int tid = threadIdx.x;
    const int gid  = blockIdx.x >> 1;
    const int half = blockIdx.x & 1;
    const int h = gid & (HH - 1);
    const int t = (gid >> 3) % TT;
    const int b = gid / (HH * TT);

    if (tid < DD * DD) {
        sWv[tid] = Wv[tid];
        sWk[tid] = Wk[tid];
        sWq[tid] = Wq[tid];
    }
    __syncthreads();

    const size_t base = ((size_t)b * NN * TT + t) * EE + (size_t)h * DD;
    const int rowstride = TT * EE;  // 1536 floats between nodes
    const int koff = half * NK;

    // ---- Project this CTA's 256 keys' K and V (transposed); 1 row/thread ----
    {
        const int r = tid;   // local key index 0..255
        const float4* kp = (const float4*)(Kg + base + (size_t)(koff + r) * rowstride);
        const float4* vp = (const float4*)(Vg + base + (size_t)(koff + r) * rowstride);
        float4 ka = kp[0], kb = kp[1];
        float4 va = vp[0], vb = vp[1];
        float kr[8] = {ka.x, ka.y, ka.z, ka.w, kb.x, kb.y, kb.z, kb.w};
        float vr[8] = {va.x, va.y, va.z, va.w, vb.x, vb.y, vb.z, vb.w};
        #pragma unroll
        for (int i = 0; i < DD; i++) {
            float sk = 0.f, sv = 0.f;
            #pragma unroll
            for (int j = 0; j < DD; j++) {
                sk = fmaf(kr[j], sWk[i * DD + j], sk);
                sv = fmaf(vr[j], sWv[i * DD + j], sv);
            }
            sKT[i * NK + r] = sk;    // consecutive lanes -> consecutive banks
            sVT[i * NK + r] = sv;
        }
    }

    // ---- Project both queries of this thread; fold scale*log2e; pack dup ----
    u64 qpA[8], qpB[8];
    #pragma unroll
    for (int sel = 0; sel < 2; sel++) {
        const int q = tid + sel * 256;
        const float4* qptr = (const float4*)(Qg + base + (size_t)q * rowstride);
        float4 qa = qptr[0], qb = qptr[1];
        float qr[8] = {qa.x, qa.y, qa.z, qa.w, qb.x, qb.y, qb.z, qb.w};
        #pragma unroll
        for (int i = 0; i < DD; i++) {
            float s = 0.f;
            #pragma unroll
            for (int j = 0; j < DD; j++) s = fmaf(qr[j], sWq[i * DD + j], s);
            s *= (SCALE * LOG2E);
            if (sel == 0) qpA[i] = pack2(s, s); else qpB[i] = pack2(s, s);
        }
    }
    __syncthreads();

    // ---- Main loop: 4 keys / iter over this CTA's 256 keys ----
    u64 accA[8], accB[8];
    #pragma unroll
    for (int j = 0; j < 8; j++) { accA[j] = 0; accB[j] = 0; }
    u64 lpA = 0, lpB = 0;

    #pragma unroll 2
    for (int k = 0; k < NK; k += 4) {
        u64 sA01 = 0, sA23 = 0, sB01 = 0, sB23 = 0;
        #pragma unroll
        for (int j = 0; j < DD; j++) {
            ulonglong2 kv = *(const ulonglong2*)(sKT + j * NK + k);  // 4 keys @ dim j
            sA01 = fma2(kv.x, qpA[j], sA01);
            sA23 = fma2(kv.y, qpA[j], sA23);
            sB01 = fma2(kv.x, qpB[j], sB01);
            sB23 = fma2(kv.y, qpB[j], sB23);
        }
        float a0, a1, a2, a3, b0, b1, b2, b3;
        unpack2(sA01, a0, a1); unpack2(sA23, a2, a3);
        unpack2(sB01, b0, b1); unpack2(sB23, b2, b3);
        u64 pA01 = pack2(fast_exp2(a0), fast_exp2(a1));
        u64 pA23 = pack2(fast_exp2(a2), fast_exp2(a3));
        u64 pB01 = pack2(fast_exp2(b0), fast_exp2(b1));
        u64 pB23 = pack2(fast_exp2(b2), fast_exp2(b3));
        lpA = add2(lpA, pA01); lpA = add2(lpA, pA23);
        lpB = add2(lpB, pB01); lpB = add2(lpB, pB23);

        #pragma unroll
        for (int j = 0; j < DD; j++) {
            ulonglong2 vv = *(const ulonglong2*)(sVT + j * NK + k);  // 4 keys @ dim j
            accA[j] = fma2(pA01, vv.x, accA[j]);
            accA[j] = fma2(pA23, vv.y, accA[j]);
            accB[j] = fma2(pB01, vv.x, accB[j]);
            accB[j] = fma2(pB23, vv.y, accB[j]);
        }
    }

    // ---- Epilogue: store UNNORMALIZED partials + denominators ----
    float* pacc = half ? g_pacc1 : g_pacc0;
    float* pl   = half ? g_pl1   : g_pl0;
    #pragma unroll
    for (int sel = 0; sel < 2; sel++) {
        const u64* acc = sel ? accB : accA;
        u64 lp = sel ? lpB : lpA;
        const int q = tid + sel * 256;
        float l0, l1;
        unpack2(lp, l0, l1);
        float o[8];
        #pragma unroll
        for (int j = 0; j < 8; j++) {
            float x, y;
            unpack2(acc[j], x, y);
            o[j] = x + y;
        }
        float* op = pacc + base + (size_t)q * rowstride;
        ((float4*)op)[0] = make_float4(o[0], o[1], o[2], o[3]);
        ((float4*)op)[1] = make_float4(o[4], o[5], o[6], o[7]);
        // l index: ((b*NN + q)*TT + t)*HH + h
        pl[(((size_t)b * NN + q) * TT + t) * HH + h] = l0 + l1;
    }
}

// Output projection fused with partial combine:
// x[r,:] = (acc0[r,:] + acc1[r,:]) / (l0[r,h] + l1[r,h]);  y = x @ Wo^T + bo.
// (R7 proj structure, protected; staging now reads both partial buffers.)
#define PRPB 64
#define PXS 68
#define PWS 68

__global__ __launch_bounds__(256) void proj_kernel(
    const float* __restrict__ Wo, const float* __restrict__ bo, float* __restrict__ out)
{
    __shared__ float sWT[EE * PWS];
    __shared__ float sb[EE];
    __shared__ float sx[PRPB * PXS];
    __shared__ float sscale[PRPB * HH];

    const int tid = threadIdx.x;
    for (int idx = tid; idx < EE * EE; idx += 256) {
        int i = idx >> 6, j = idx & 63;
        sWT[j * PWS + i] = Wo[idx];
    }
    if (tid < EE) sb[tid] = bo[tid];

    const size_t rbase = (size_t)blockIdx.x * PRPB * EE;
    const size_t lbase = (size_t)blockIdx.x * PRPB * HH;

    // Per-(row,h) combine scale = 1 / (l0 + l1).
    for (int idx = tid; idx < PRPB * HH; idx += 256)
        sscale[idx] = 1.0f / (g_pl0[lbase + idx] + g_pl1[lbase + idx]);
    __syncthreads();

    // Stage x: combine the two partial buffers and normalize.
    #pragma unroll
    for (int idx = tid * 4; idx < PRPB * EE; idx += 256 * 4) {
        float4 a = *(const float4*)(g_pacc0 + rbase + idx);
        float4 c = *(const float4*)(g_pacc1 + rbase + idx);
        const int r = idx >> 6;
        const int col = idx & 63;           // quad lies within one h block
        const float s = sscale[r * HH + (col >> 3)];
        float* dst = sx + r * PXS + col;
        dst[0] = (a.x + c.x) * s;
        dst[1] = (a.y + c.y) * s;
        dst[2] = (a.z + c.z) * s;
        dst[3] = (a.w + c.w) * s;
    }
    __syncthreads();

    const int w = tid >> 5;
    const int lane = tid & 31;
    const int i0 = w * 8;

    u64 aA[4], aB[4];
    {
        u64 b01 = pack2(sb[i0 + 0], sb[i0 + 1]);
        u64 b23 = pack2(sb[i0 + 2], sb[i0 + 3]);
        u64 b45 = pack2(sb[i0 + 4], sb[i0 + 5]);
        u64 b67 = pack2(sb[i0 + 6], sb[i0 + 7]);
        aA[0] = b01; aA[1] = b23; aA[2] = b45; aA[3] = b67;
        aB[0] = b01; aB[1] = b23; aB[2] = b45; aB[3] = b67;
    }

    const float* xA = sx + lane * PXS;
    const float* xB = sx + (lane + 32) * PXS;
    #pragma unroll 4
    for (int j4 = 0; j4 < EE; j4 += 4) {
        float4 xa4 = *(const float4*)(xA + j4);
        float4 xb4 = *(const float4*)(xB + j4);
        const float xa[4] = {xa4.x, xa4.y, xa4.z, xa4.w};
        const float xb[4] = {xb4.x, xb4.y, xb4.z, xb4.w};
        #pragma unroll
        for (int jj = 0; jj < 4; jj++) {
            const ulonglong2* wp = (const ulonglong2*)(sWT + (j4 + jj) * PWS + i0);
            ulonglong2 wa = wp[0];
            ulonglong2 wb = wp[1];
            u64 xpa = pack2(xa[jj], xa[jj]);
            u64 xpb = pack2(xb[jj], xb[jj]);
            aA[0] = fma2(xpa, wa.x, aA[0]);
            aA[1] = fma2(xpa, wa.y, aA[1]);
            aA[2] = fma2(xpa, wb.x, aA[2]);
            aA[3] = fma2(xpa, wb.y, aA[3]);
            aB[0] = fma2(xpb, wa.x, aB[0]);
            aB[1] = fma2(xpb, wa.y, aB[1]);
            aB[2] = fma2(xpb, wb.x, aB[2]);
            aB[3] = fma2(xpb, wb.y, aB[3]);
        }
    }

    __syncthreads();
    #pragma unroll
    for (int r = 0; r < 2; r++) {
        const u64* a = r ? aB : aA;
        float* dst = sx + (lane + r * 32) * PXS + i0;
        #pragma unroll
        for (int c = 0; c < 4; c++) {
            float lo, hi;
            unpack2(a[c], lo, hi);
            dst[2 * c] = lo;
            dst[2 * c + 1] = hi;
        }
    }
    __syncthreads();
    #pragma unroll
    for (int idx = tid * 4; idx < PRPB * EE; idx += 256 * 4) {
        const float* src = sx + (idx >> 6) * PXS + (idx & 63);
        *(float4*)(out + rbase + idx) = make_float4(src[0], src[1], src[2], src[3]);
    }
}

extern "C" void kernel_launch(void* const* d_in, const int* in_sizes, int n_in,
                              void* d_out, int out_size)
{
    const float* values = (const float*)d_in[0];
    const float* keys   = (const float*)d_in[1];
    const float* query  = (const float*)d_in[2];
    const float* Wv     = (const float*)d_in[3];
    const float* Wk     = (const float*)d_in[4];
    const float* Wq     = (const float*)d_in[5];
    const float* Wo     = (const float*)d_in[6];
    const float* bo     = (const float*)d_in[7];

    attn_kernel<<<BN * TT * HH * 2, 256>>>(values, keys, query, Wv, Wk, Wq);
    proj_kernel<<<BN * NN * TT / PRPB, 256>>>(Wo, bo, (float*)d_out);
}

// round 14
// speedup vs baseline: 1.3473x; 1.0342x over previous
#include <cuda_runtime.h>

#define BN 2
#define NN 512
#define TT 24
#define HH 8
#define DD 8
#define EE 64
#define SCALE 0.125f
#define LOG2E 1.44269504088896340736f

typedef unsigned long long u64;

// Intermediate per-head attention output (b, n, t, e) before output projection.
__device__ float g_mid[BN * NN * TT * EE];

__device__ __forceinline__ float fast_exp2(float x) {
    float y;
    asm("ex2.approx.f32 %0, %1;" : "=f"(y) : "f"(x));
    return y;
}
__device__ __forceinline__ u64 pack2(float a, float b) {
    u64 r; asm("mov.b64 %0, {%1, %2};" : "=l"(r) : "f"(a), "f"(b)); return r;
}
__device__ __forceinline__ void unpack2(u64 v, float& a, float& b) {
    asm("mov.b64 {%0, %1}, %2;" : "=f"(a), "=f"(b) : "l"(v));
}
__device__ __forceinline__ u64 fma2(u64 a, u64 b, u64 c) {
    u64 d; asm("fma.rn.f32x2 %0, %1, %2, %3;" : "=l"(d) : "l"(a), "l"(b), "l"(c)); return d;
}
__device__ __forceinline__ u64 add2(u64 a, u64 b) {
    u64 d; asm("add.rn.f32x2 %0, %1, %2;" : "=l"(d) : "l"(a), "l"(b)); return d;
}

// One CTA per (b, t, h) group: 256 threads, 2 queries per thread. grid = 384.
// (R3/R7 configuration, measured ~88.5us: FROZEN.)
__global__ __launch_bounds__(256, 2) void attn_kernel(
    const float* __restrict__ Vg, const float* __restrict__ Kg, const float* __restrict__ Qg,
    const float* __restrict__ Wv, const float* __restrict__ Wk, const float* __restrict__ Wq)
{
    __shared__ float sKT[DD * NN];   // sKT[j*NN + k]
    __shared__ float sVT[DD * NN];   // sVT[j*NN + k]
    __shared__ float sWk[DD * DD], sWv[DD * DD], sWq[DD * DD];

    const int tid = threadIdx.x;
    const int gid = blockIdx.x;
    const int h = gid & (HH - 1);
    const int t = (gid >> 3) % TT;
    const int b = gid / (HH * TT);

    if (tid < DD * DD) {
        sWv[tid] = Wv[tid];
        sWk[tid] = Wk[tid];
        sWq[tid] = Wq[tid];
    }
    __syncthreads();

    const size_t base = ((size_t)b * NN * TT + t) * EE + (size_t)h * DD;
    const int rowstride = TT * EE;  // 1536 floats between nodes

    // ---- Project K and V (both transposed) for all 512 nodes ----
    for (int r = tid; r < NN; r += 256) {
        const float4* kp = (const float4*)(Kg + base + (size_t)r * rowstride);
        const float4* vp = (const float4*)(Vg + base + (size_t)r * rowstride);
        float4 ka = kp[0], kb = kp[1];
        float4 va = vp[0], vb = vp[1];
        float kr[8] = {ka.x, ka.y, ka.z, ka.w, kb.x, kb.y, kb.z, kb.w};
        float vr[8] = {va.x, va.y, va.z, va.w, vb.x, vb.y, vb.z, vb.w};
        #pragma unroll
        for (int i = 0; i < DD; i++) {
            float sk = 0.f, sv = 0.f;
            #pragma unroll
            for (int j = 0; j < DD; j++) {
                sk = fmaf(kr[j], sWk[i * DD + j], sk);
                sv = fmaf(vr[j], sWv[i * DD + j], sv);
            }
            sKT[i * NN + r] = sk;    // consecutive lanes -> consecutive banks
            sVT[i * NN + r] = sv;
        }
    }

    // ---- Project both queries of this thread; fold scale*log2e; pack dup ----
    u64 qpA[8], qpB[8];
    #pragma unroll
    for (int sel = 0; sel < 2; sel++) {
        const int q = tid + sel * 256;
        const float4* qptr = (const float4*)(Qg + base + (size_t)q * rowstride);
        float4 qa = qptr[0], qb = qptr[1];
        float qr[8] = {qa.x, qa.y, qa.z, qa.w, qb.x, qb.y, qb.z, qb.w};
        #pragma unroll
        for (int i = 0; i < DD; i++) {
            float s = 0.f;
            #pragma unroll
            for (int j = 0; j < DD; j++) s = fmaf(qr[j], sWq[i * DD + j], s);
            s *= (SCALE * LOG2E);
            if (sel == 0) qpA[i] = pack2(s, s); else qpB[i] = pack2(s, s);
        }
    }
    __syncthreads();

    // ---- Main loop: 4 keys / iter, 2 queries / thread, packed f32x2.
    //      All SMEM reads are LDS.128 warp broadcasts shared by both queries.
    u64 accA[8], accB[8];
    #pragma unroll
    for (int j = 0; j < 8; j++) { accA[j] = 0; accB[j] = 0; }
    u64 lpA = 0, lpB = 0;

    #pragma unroll 2
    for (int k = 0; k < NN; k += 4) {
        u64 sA01 = 0, sA23 = 0, sB01 = 0, sB23 = 0;
        #pragma unroll
        for (int j = 0; j < DD; j++) {
            ulonglong2 kv = *(const ulonglong2*)(sKT + j * NN + k);  // 4 keys @ dim j
            sA01 = fma2(kv.x, qpA[j], sA01);
            sA23 = fma2(kv.y, qpA[j], sA23);
            sB01 = fma2(kv.x, qpB[j], sB01);
            sB23 = fma2(kv.y, qpB[j], sB23);
        }
        float a0, a1, a2, a3, b0, b1, b2, b3;
        unpack2(sA01, a0, a1); unpack2(sA23, a2, a3);
        unpack2(sB01, b0, b1); unpack2(sB23, b2, b3);
        u64 pA01 = pack2(fast_exp2(a0), fast_exp2(a1));
        u64 pA23 = pack2(fast_exp2(a2), fast_exp2(a3));
        u64 pB01 = pack2(fast_exp2(b0), fast_exp2(b1));
        u64 pB23 = pack2(fast_exp2(b2), fast_exp2(b3));
        lpA = add2(lpA, pA01); lpA = add2(lpA, pA23);
        lpB = add2(lpB, pB01); lpB = add2(lpB, pB23);

        #pragma unroll
        for (int j = 0; j < DD; j++) {
            ulonglong2 vv = *(const ulonglong2*)(sVT + j * NN + k);  // 4 keys @ dim j
            accA[j] = fma2(pA01, vv.x, accA[j]);
            accA[j] = fma2(pA23, vv.y, accA[j]);
            accB[j] = fma2(pB01, vv.x, accB[j]);
            accB[j] = fma2(pB23, vv.y, accB[j]);
        }
    }

    // ---- Epilogue: fold packed halves, normalize, store both query rows ----
    #pragma unroll
    for (int sel = 0; sel < 2; sel++) {
        const u64* acc = sel ? accB : accA;
        u64 lp = sel ? lpB : lpA;
        float l0, l1;
        unpack2(lp, l0, l1);
        const float inv = 1.0f / (l0 + l1);
        float o[8];
        #pragma unroll
        for (int j = 0; j < 8; j++) {
            float x, y;
            unpack2(acc[j], x, y);
            o[j] = (x + y) * inv;
        }
        float* op = g_mid + base + (size_t)(tid + sel * 256) * rowstride;
        ((float4*)op)[0] = make_float4(o[0], o[1], o[2], o[3]);
        ((float4*)op)[1] = make_float4(o[4], o[5], o[6], o[7]);
    }
}

// Output projection: y[r,:] = x[r,:] @ Wo^T + bo, R = B*N*T = 24576 rows.
// 512 threads, 64 rows/CTA (grid 384 -> 42 warps/SM). Warps 0-7 take rows
// 0-31, warps 8-15 rows 32-63; each warp owns 8 output cols (W LDS.128
// broadcasts). x via LDS.128 (conflict-free phases). SMEM-bounced stores.
#define PRPB 64
#define PXS 68
#define PWS 68

__global__ __launch_bounds__(512) void proj_kernel(
    const float* __restrict__ Wo, const float* __restrict__ bo, float* __restrict__ out)
{
    __shared__ float sWT[EE * PWS];    // sWT[j*PWS + i] = Wo[i*EE + j]  (17.4 KB)
    __shared__ float sb[EE];
    __shared__ float sx[PRPB * PXS];   // 17.4 KB

    const int tid = threadIdx.x;
    for (int idx = tid; idx < EE * EE; idx += 512) {
        int i = idx >> 6, j = idx & 63;
        sWT[j * PWS + i] = Wo[idx];
    }
    if (tid < EE) sb[tid] = bo[tid];

    const size_t rbase = (size_t)blockIdx.x * PRPB * EE;
    // Stage x: 4096 floats, coalesced float4 reads, padded-row writes.
    #pragma unroll
    for (int idx = tid * 4; idx < PRPB * EE; idx += 512 * 4) {
        float4 v = *(const float4*)(g_mid + rbase + idx);
        float* dst = sx + (idx >> 6) * PXS + (idx & 63);
        dst[0] = v.x; dst[1] = v.y; dst[2] = v.z; dst[3] = v.w;
    }
    __syncthreads();

    const int wid = tid >> 5;
    const int lane = tid & 31;
    const int row = ((wid >> 3) << 5) + lane;   // warps 0-7 -> rows 0-31; 8-15 -> 32-63
    const int i0 = (wid & 7) * 8;               // 8 output columns per warp

    u64 a01 = pack2(sb[i0 + 0], sb[i0 + 1]);
    u64 a23 = pack2(sb[i0 + 2], sb[i0 + 3]);
    u64 a45 = pack2(sb[i0 + 4], sb[i0 + 5]);
    u64 a67 = pack2(sb[i0 + 6], sb[i0 + 7]);

    const float* xr = sx + row * PXS;
    #pragma unroll 4
    for (int j4 = 0; j4 < EE; j4 += 4) {
        float4 xv = *(const float4*)(xr + j4);    // conflict-free phases
        const float xs[4] = {xv.x, xv.y, xv.z, xv.w};
        #pragma unroll
        for (int jj = 0; jj < 4; jj++) {
            const ulonglong2* wp = (const ulonglong2*)(sWT + (j4 + jj) * PWS + i0);  // broadcast
            ulonglong2 wa = wp[0];
            ulonglong2 wb = wp[1];
            u64 xp = pack2(xs[jj], xs[jj]);
            a01 = fma2(xp, wa.x, a01);
            a23 = fma2(xp, wa.y, a23);
            a45 = fma2(xp, wb.x, a45);
            a67 = fma2(xp, wb.y, a67);
        }
    }

    // ---- Bounce results through SMEM so global stores are coalesced ----
    __syncthreads();   // done reading sx as input
    {
        float* dst = sx + row * PXS + i0;
        float lo, hi;
        unpack2(a01, lo, hi); dst[0] = lo; dst[1] = hi;
        unpack2(a23, lo, hi); dst[2] = lo; dst[3] = hi;
        unpack2(a45, lo, hi); dst[4] = lo; dst[5] = hi;
        unpack2(a67, lo, hi); dst[6] = lo; dst[7] = hi;
    }
    __syncthreads();
    #pragma unroll
    for (int idx = tid * 4; idx < PRPB * EE; idx += 512 * 4) {
        const float* src = sx + (idx >> 6) * PXS + (idx & 63);
        *(float4*)(out + rbase + idx) = make_float4(src[0], src[1], src[2], src[3]);
    }
}

extern "C" void kernel_launch(void* const* d_in, const int* in_sizes, int n_in,
                              void* d_out, int out_size)
{
    const float* values = (const float*)d_in[0];
    const float* keys   = (const float*)d_in[1];
    const float* query  = (const float*)d_in[2];
    const float* Wv     = (const float*)d_in[3];
    const float* Wk     = (const float*)d_in[4];
    const float* Wq     = (const float*)d_in[5];
    const float* Wo     = (const float*)d_in[6];
    const float* bo     = (const float*)d_in[7];

    attn_kernel<<<BN * TT * HH, 256>>>(values, keys, query, Wv, Wk, Wq);
    proj_kernel<<<BN * NN * TT / PRPB, 512>>>(Wo, bo, (float*)d_out);
}

// round 15
// speedup vs baseline: 1.3641x; 1.0125x over previous
#include <cuda_runtime.h>

#define BN 2
#define NN 512
#define TT 24
#define HH 8
#define DD 8
#define EE 64
#define SCALE 0.125f
#define LOG2E 1.44269504088896340736f

#define GRID_ATTN (BN * TT * HH)          // 384, bids 0..383 (b-major)
#define PRPB 64
#define GRID_PROJ (BN * NN * TT / PRPB)   // 384, bids 384..767
#define PXS 68
#define PWS 68
#define ATTN_PER_BATCH (TT * HH)          // 192

typedef unsigned long long u64;

// Intermediate per-head attention output (b, n, t, e) before output projection.
__device__ float g_mid[BN * NN * TT * EE];
// Per-batch completion counters for attn CTAs (reset each launch).
__device__ int g_done[BN];

__device__ __forceinline__ float fast_exp2(float x) {
    float y;
    asm("ex2.approx.f32 %0, %1;" : "=f"(y) : "f"(x));
    return y;
}
__device__ __forceinline__ u64 pack2(float a, float b) {
    u64 r; asm("mov.b64 %0, {%1, %2};" : "=l"(r) : "f"(a), "f"(b)); return r;
}
__device__ __forceinline__ void unpack2(u64 v, float& a, float& b) {
    asm("mov.b64 {%0, %1}, %2;" : "=f"(a), "=f"(b) : "l"(v));
}
__device__ __forceinline__ u64 fma2(u64 a, u64 b, u64 c) {
    u64 d; asm("fma.rn.f32x2 %0, %1, %2, %3;" : "=l"(d) : "l"(a), "l"(b), "l"(c)); return d;
}
__device__ __forceinline__ u64 add2(u64 a, u64 b) {
    u64 d; asm("add.rn.f32x2 %0, %1, %2;" : "=l"(d) : "l"(a), "l"(b)); return d;
}

__global__ void reset_kernel() {
    g_done[0] = 0;
    g_done[1] = 0;
}

// SMEM pool shared by both roles (max of attn 33.5KB / proj 35.1KB layouts).
#define POOL_FLOATS (EE * PWS + EE + PRPB * PXS)   // 8768 floats (proj layout)

__global__ __launch_bounds__(256, 2) void fused_kernel(
    const float* __restrict__ Vg, const float* __restrict__ Kg, const float* __restrict__ Qg,
    const float* __restrict__ Wv, const float* __restrict__ Wk, const float* __restrict__ Wq,
    const float* __restrict__ Wo, const float* __restrict__ bo, float* __restrict__ out)
{
    __shared__ float pool[POOL_FLOATS];
    __shared__ float sWsmall[3 * DD * DD];

    const int tid = threadIdx.x;

    if (blockIdx.x < GRID_ATTN) {
        // ===================== ATTENTION ROLE (R7 verbatim) =====================
        float* sKT = pool;                 // [DD*NN]
        float* sVT = pool + DD * NN;       // [DD*NN]
        float* sWk = sWsmall;
        float* sWv = sWsmall + DD * DD;
        float* sWq = sWsmall + 2 * DD * DD;

        const int gid = blockIdx.x;
        const int h = gid & (HH - 1);
        const int t = (gid >> 3) % TT;
        const int b = gid / (HH * TT);     // b-major: bids 0..191 = b0

        if (tid < DD * DD) {
            sWv[tid] = Wv[tid];
            sWk[tid] = Wk[tid];
            sWq[tid] = Wq[tid];
        }
        __syncthreads();

        const size_t base = ((size_t)b * NN * TT + t) * EE + (size_t)h * DD;
        const int rowstride = TT * EE;

        for (int r = tid; r < NN; r += 256) {
            const float4* kp = (const float4*)(Kg + base + (size_t)r * rowstride);
            const float4* vp = (const float4*)(Vg + base + (size_t)r * rowstride);
            float4 ka = kp[0], kb = kp[1];
            float4 va = vp[0], vb = vp[1];
            float kr[8] = {ka.x, ka.y, ka.z, ka.w, kb.x, kb.y, kb.z, kb.w};
            float vr[8] = {va.x, va.y, va.z, va.w, vb.x, vb.y, vb.z, vb.w};
            #pragma unroll
            for (int i = 0; i < DD; i++) {
                float sk = 0.f, sv = 0.f;
                #pragma unroll
                for (int j = 0; j < DD; j++) {
                    sk = fmaf(kr[j], sWk[i * DD + j], sk);
                    sv = fmaf(vr[j], sWv[i * DD + j], sv);
                }
                sKT[i * NN + r] = sk;
                sVT[i * NN + r] = sv;
            }
        }

        u64 qpA[8], qpB[8];
        #pragma unroll
        for (int sel = 0; sel < 2; sel++) {
            const int q = tid + sel * 256;
            const float4* qptr = (const float4*)(Qg + base + (size_t)q * rowstride);
            float4 qa = qptr[0], qb = qptr[1];
            float qr[8] = {qa.x, qa.y, qa.z, qa.w, qb.x, qb.y, qb.z, qb.w};
            #pragma unroll
            for (int i = 0; i < DD; i++) {
                float s = 0.f;
                #pragma unroll
                for (int j = 0; j < DD; j++) s = fmaf(qr[j], sWq[i * DD + j], s);
                s *= (SCALE * LOG2E);
                if (sel == 0) qpA[i] = pack2(s, s); else qpB[i] = pack2(s, s);
            }
        }
        __syncthreads();

        u64 accA[8], accB[8];
        #pragma unroll
        for (int j = 0; j < 8; j++) { accA[j] = 0; accB[j] = 0; }
        u64 lpA = 0, lpB = 0;

        #pragma unroll 2
        for (int k = 0; k < NN; k += 4) {
            u64 sA01 = 0, sA23 = 0, sB01 = 0, sB23 = 0;
            #pragma unroll
            for (int j = 0; j < DD; j++) {
                ulonglong2 kv = *(const ulonglong2*)(sKT + j * NN + k);
                sA01 = fma2(kv.x, qpA[j], sA01);
                sA23 = fma2(kv.y, qpA[j], sA23);
                sB01 = fma2(kv.x, qpB[j], sB01);
                sB23 = fma2(kv.y, qpB[j], sB23);
            }
            float a0, a1, a2, a3, b0, b1, b2, b3;
            unpack2(sA01, a0, a1); unpack2(sA23, a2, a3);
            unpack2(sB01, b0, b1); unpack2(sB23, b2, b3);
            u64 pA01 = pack2(fast_exp2(a0), fast_exp2(a1));
            u64 pA23 = pack2(fast_exp2(a2), fast_exp2(a3));
            u64 pB01 = pack2(fast_exp2(b0), fast_exp2(b1));
            u64 pB23 = pack2(fast_exp2(b2), fast_exp2(b3));
            lpA = add2(lpA, pA01); lpA = add2(lpA, pA23);
            lpB = add2(lpB, pB01); lpB = add2(lpB, pB23);

            #pragma unroll
            for (int j = 0; j < DD; j++) {
                ulonglong2 vv = *(const ulonglong2*)(sVT + j * NN + k);
                accA[j] = fma2(pA01, vv.x, accA[j]);
                accA[j] = fma2(pA23, vv.y, accA[j]);
                accB[j] = fma2(pB01, vv.x, accB[j]);
                accB[j] = fma2(pB23, vv.y, accB[j]);
            }
        }

        #pragma unroll
        for (int sel = 0; sel < 2; sel++) {
            const u64* acc = sel ? accB : accA;
            u64 lp = sel ? lpB : lpA;
            float l0, l1;
            unpack2(lp, l0, l1);
            const float inv = 1.0f / (l0 + l1);
            float o[8];
            #pragma unroll
            for (int j = 0; j < 8; j++) {
                float x, y;
                unpack2(acc[j], x, y);
                o[j] = (x + y) * inv;
            }
            float* op = g_mid + base + (size_t)(tid + sel * 256) * rowstride;
            ((float4*)op)[0] = make_float4(o[0], o[1], o[2], o[3]);
            ((float4*)op)[1] = make_float4(o[4], o[5], o[6], o[7]);
        }

        // Publish completion: stores -> fence -> barrier -> counter.
        __threadfence();
        __syncthreads();
        if (tid == 0) atomicAdd(&g_done[b], 1);

    } else {
        // ===================== PROJECTION ROLE (R7 verbatim + gate) =============
        float* sWT = pool;                                  // [EE*PWS]
        float* sb  = pool + EE * PWS;                       // [EE]
        float* sx  = pool + EE * PWS + EE;                  // [PRPB*PXS]

        const int pb = blockIdx.x - GRID_ATTN;
        const size_t rbase = (size_t)pb * PRPB * EE;
        const int batch = (pb * PRPB) / (NN * TT);          // rows 0..12287 = b0

        // Stage W and bias BEFORE gating (independent of g_mid).
        for (int idx = tid; idx < EE * EE; idx += 256) {
            int i = idx >> 6, j = idx & 63;
            sWT[j * PWS + i] = Wo[idx];
        }
        if (tid < EE) sb[tid] = bo[tid];

        // Gate: wait until all 192 attn CTAs of this batch published.
        if (tid == 0) {
            while (atomicAdd(&g_done[batch], 0) < ATTN_PER_BATCH)
                __nanosleep(200);
            __threadfence();   // acquire: make attn's g_mid stores visible
        }
        __syncthreads();

        #pragma unroll
        for (int idx = tid * 4; idx < PRPB * EE; idx += 256 * 4) {
            float4 v = *(const float4*)(g_mid + rbase + idx);
            float* dst = sx + (idx >> 6) * PXS + (idx & 63);
            dst[0] = v.x; dst[1] = v.y; dst[2] = v.z; dst[3] = v.w;
        }
        __syncthreads();

        const int w = tid >> 5;
        const int lane = tid & 31;
        const int i0 = w * 8;

        u64 aA[4], aB[4];
        {
            u64 b01 = pack2(sb[i0 + 0], sb[i0 + 1]);
            u64 b23 = pack2(sb[i0 + 2], sb[i0 + 3]);
            u64 b45 = pack2(sb[i0 + 4], sb[i0 + 5]);
            u64 b67 = pack2(sb[i0 + 6], sb[i0 + 7]);
            aA[0] = b01; aA[1] = b23; aA[2] = b45; aA[3] = b67;
            aB[0] = b01; aB[1] = b23; aB[2] = b45; aB[3] = b67;
        }

        const float* xA = sx + lane * PXS;
        const float* xB = sx + (lane + 32) * PXS;
        #pragma unroll 4
        for (int j4 = 0; j4 < EE; j4 += 4) {
            float4 xa4 = *(const float4*)(xA + j4);
            float4 xb4 = *(const float4*)(xB + j4);
            const float xa[4] = {xa4.x, xa4.y, xa4.z, xa4.w};
            const float xb[4] = {xb4.x, xb4.y, xb4.z, xb4.w};
            #pragma unroll
            for (int jj = 0; jj < 4; jj++) {
                const ulonglong2* wp = (const ulonglong2*)(sWT + (j4 + jj) * PWS + i0);
                ulonglong2 wa = wp[0];
                ulonglong2 wb = wp[1];
                u64 xpa = pack2(xa[jj], xa[jj]);
                u64 xpb = pack2(xb[jj], xb[jj]);
                aA[0] = fma2(xpa, wa.x, aA[0]);
                aA[1] = fma2(xpa, wa.y, aA[1]);
                aA[2] = fma2(xpa, wb.x, aA[2]);
                aA[3] = fma2(xpa, wb.y, aA[3]);
                aB[0] = fma2(xpb, wa.x, aB[0]);
                aB[1] = fma2(xpb, wa.y, aB[1]);
                aB[2] = fma2(xpb, wb.x, aB[2]);
                aB[3] = fma2(xpb, wb.y, aB[3]);
            }
        }

        __syncthreads();
        #pragma unroll
        for (int r = 0; r < 2; r++) {
            const u64* a = r ? aB : aA;
            float* dst = sx + (lane + r * 32) * PXS + i0;
            #pragma unroll
            for (int c = 0; c < 4; c++) {
                float lo, hi;
                unpack2(a[c], lo, hi);
                dst[2 * c] = lo;
                dst[2 * c + 1] = hi;
            }
        }
        __syncthreads();
        #pragma unroll
        for (int idx = tid * 4; idx < PRPB * EE; idx += 256 * 4) {
            const float* src = sx + (idx >> 6) * PXS + (idx & 63);
            *(float4*)(out + rbase + idx) = make_float4(src[0], src[1], src[2], src[3]);
        }
    }
}

extern "C" void kernel_launch(void* const* d_in, const int* in_sizes, int n_in,
                              void* d_out, int out_size)
{
    const float* values = (const float*)d_in[0];
    const float* keys   = (const float*)d_in[1];
    const float* query  = (const float*)d_in[2];
    const float* Wv     = (const float*)d_in[3];
    const float* Wk     = (const float*)d_in[4];
    const float* Wq     = (const float*)d_in[5];
    const float* Wo     = (const float*)d_in[6];
    const float* bo     = (const float*)d_in[7];

    reset_kernel<<<1, 1>>>();
    fused_kernel<<<GRID_ATTN + GRID_PROJ, 256>>>(
        values, keys, query, Wv, Wk, Wq, Wo, bo, (float*)d_out);
}